// round 5
// baseline (speedup 1.0000x reference)
#include <cuda_runtime.h>

// I5Pool: out[b,c,h,w] = max_{j<=w} x[b,c,h,j] * guide[b,0,h,j]
// x [8,256,128,128] fp32, guide [8,1,128,128] fp32.
// 8 channel-rows per warp (one shared guide load); float4; 8 interleaved
// warp shuffle max-scans; x/out on streaming path (__ldcs/__stcs).
// 9 front-batched independent loads per thread -> deep MLP, long
// same-direction DRAM bursts.

#define B_ 8
#define C_ 256
#define H_ 128
#define W_ 128
#define ROWS  (B_ * C_ * H_)     // 262144
#define R8    (ROWS / 8)         // 32768 warps

__global__ void __launch_bounds__(256) I5Pool_kernel(
    const float* __restrict__ x,
    const float* __restrict__ guide,
    float* __restrict__ out)
{
    const int wg   = (blockIdx.x * blockDim.x + threadIdx.x) >> 5;
    const int lane = threadIdx.x & 31;
    if (wg >= R8) return;

    // wg = b*(C_/8 * H_) + c8*H_ + h ; rows are c = 8*c8 + r
    const int h  = wg & (H_ - 1);
    const int t  = wg >> 7;          // b*(C_/8) + c8
    const int b  = t >> 5;           // / 32
    const int c8 = t & 31;

    const size_t rstride = (size_t)H_ * W_;
    const size_t row0 = (((size_t)b * C_ + 8 * c8) * H_ + h) * W_;
    const size_t grow = ((size_t)b * H_ + h) * W_;

    // Front-batch all 9 loads (1 guide cached + 8 x streaming)
    const float4 gv = reinterpret_cast<const float4*>(guide + grow)[lane];
    float4 xv[8];
    #pragma unroll
    for (int r = 0; r < 8; r++)
        xv[r] = __ldcs(reinterpret_cast<const float4*>(x + row0 + r * rstride) + lane);

    // local serial prefix-max per row (4 elems each)
    float v0[8], v1[8], v2[8], v3[8];
    #pragma unroll
    for (int r = 0; r < 8; r++) {
        v0[r] = xv[r].x * gv.x;
        v1[r] = fmaxf(v0[r], xv[r].y * gv.y);
        v2[r] = fmaxf(v1[r], xv[r].z * gv.z);
        v3[r] = fmaxf(v2[r], xv[r].w * gv.w);
    }

    // 8 interleaved warp inclusive max-scans on lane totals
    float m[8];
    #pragma unroll
    for (int r = 0; r < 8; r++) m[r] = v3[r];
    #pragma unroll
    for (int d = 1; d < 32; d <<= 1) {
        float o[8];
        #pragma unroll
        for (int r = 0; r < 8; r++) o[r] = __shfl_up_sync(0xffffffffu, m[r], d);
        if (lane >= d) {
            #pragma unroll
            for (int r = 0; r < 8; r++) m[r] = fmaxf(m[r], o[r]);
        }
    }

    // exclusive prefix per row, fold, store (4KB write burst per warp)
    const float ninf = __int_as_float(0xff800000);
    #pragma unroll
    for (int r = 0; r < 8; r++) {
        float p = __shfl_up_sync(0xffffffffu, m[r], 1);
        if (lane == 0) p = ninf;
        float4 o;
        o.x = fmaxf(v0[r], p);
        o.y = fmaxf(v1[r], p);
        o.z = fmaxf(v2[r], p);
        o.w = fmaxf(v3[r], p);
        __stcs(reinterpret_cast<float4*>(out + row0 + r * rstride) + lane, o);
    }
}

extern "C" void kernel_launch(void* const* d_in, const int* in_sizes, int n_in,
                              void* d_out, int out_size)
{
    const float* x     = (const float*)d_in[0];
    const float* guide = (const float*)d_in[1];
    float* out         = (float*)d_out;

    const int threads = 256;                 // 8 warps/block
    const int blocks  = (R8 * 32) / threads; // 4096 blocks
    I5Pool_kernel<<<blocks, threads>>>(x, guide, out);
}